// round 14
// baseline (speedup 1.0000x reference)
#include <cuda_runtime.h>
#include <cstdint>

#define CIN  8
#define COUT 8
#define HH   1024
#define WW   1024
#define KK   31

#define NT   256                 // 8 warps
#define RY   8                   // output rows per CTA
#define TXC  256                 // output cols per CTA (8 warps x 32 px)
#define NROWS (RY + 30)          // 38 staged input rows
#define WPC   146                // packed words per parity copy
#define ROWB  (2 * WPC * 4)      // 1168 bytes per row (copy0[146], copy1[146])

#define OFF_SA 0
#define SA_BYTES (NROWS * ROWB)              // 44384
#define OFF_W   ((SA_BYTES + 127) & ~127)    // 44416
#define W_BYTES (31 * 32 * 16)               // 15872  (uint4 per (i,lane))
#define SMEM_TOTAL (OFF_W + W_BYTES)         // 60288

static __device__ __forceinline__ uint32_t smem_u32(const void* p) {
    uint32_t a;
    asm("{ .reg .u64 t; cvta.to.shared.u64 t, %1; cvt.u32.u64 %0, t; }" : "=r"(a) : "l"(p));
    return a;
}
// pack two fp32 -> (f16lo, f16hi) in one b32
static __device__ __forceinline__ uint32_t packh(float lo, float hi) {
    uint32_t r;
    asm("{ .reg .f16 l, h; cvt.rn.f16.f32 l, %1; cvt.rn.f16.f32 h, %2; mov.b32 %0, {l, h}; }"
        : "=r"(r) : "f"(lo), "f"(hi));
    return r;
}
static __device__ __forceinline__ uint32_t lds32(uint32_t a) {
    uint32_t v;
    asm volatile("ld.shared.b32 %0, [%1];" : "=r"(v) : "r"(a));
    return v;
}
static __device__ __forceinline__ uint2 lds64(uint32_t a) {
    uint2 v;
    asm volatile("ld.shared.v2.b32 {%0,%1}, [%2];" : "=r"(v.x), "=r"(v.y) : "r"(a));
    return v;
}
static __device__ __forceinline__ uint4 lds128(uint32_t a) {
    uint4 v;
    asm volatile("ld.shared.v4.b32 {%0,%1,%2,%3}, [%4];"
                 : "=r"(v.x), "=r"(v.y), "=r"(v.z), "=r"(v.w) : "r"(a));
    return v;
}
// D(16px x 8co) += A(16px x 16k) * B(16k x 8co), fp16 in, fp32 acc
static __device__ __forceinline__ void mma16(float* c,
                                             uint32_t a0, uint32_t a1,
                                             uint32_t a2, uint32_t a3,
                                             uint32_t bx, uint32_t by) {
    asm volatile("mma.sync.aligned.m16n8k16.row.col.f32.f16.f16.f32 "
                 "{%0,%1,%2,%3}, {%4,%5,%6,%7}, {%8,%9}, {%0,%1,%2,%3};"
                 : "+f"(c[0]), "+f"(c[1]), "+f"(c[2]), "+f"(c[3])
                 : "r"(a0), "r"(a1), "r"(a2), "r"(a3), "r"(bx), "r"(by));
}

__global__ __launch_bounds__(NT, 2)
void conv_mma_kernel(const float* __restrict__ sig,
                     const float* __restrict__ wgt,
                     const float* __restrict__ bias,
                     float* __restrict__ out)
{
    extern __shared__ char smem[];
    const uint32_t sb = smem_u32(smem);
    const int tid  = threadIdx.x;
    const int wid  = tid >> 5;
    const int lane = tid & 31;
    const int X0 = blockIdx.x * TXC;
    const int Y0 = blockIdx.y * RY;
    const int ci = blockIdx.z;

    // ---- stage input rows as fp16, two parity-shifted packed copies ----
    const float* sigc = sig + (size_t)ci * (HH * WW);
    for (int idx = tid; idx < NROWS * 2 * WPC; idx += NT) {
        const int rr  = idx / (2 * WPC);
        const int rem = idx - rr * (2 * WPC);
        const int cp  = rem / WPC;
        const int w   = rem - cp * WPC;
        const int gr  = Y0 - 15 + rr;
        const int lc0 = 2 * w + cp;
        float v0 = 0.0f, v1 = 0.0f;
        if ((unsigned)gr < (unsigned)HH) {
            const float* srow = sigc + (size_t)gr * WW;
            const int g0 = X0 - 16 + lc0;
            const int g1 = g0 + 1;
            if ((unsigned)g0 < (unsigned)WW) v0 = srow[g0];
            if ((unsigned)g1 < (unsigned)WW) v1 = srow[g1];
        }
        ((uint32_t*)(smem + OFF_SA))[rr * (2 * WPC) + cp * WPC + w] = packh(v0, v1);
    }

    // ---- stage B fragments per lane as uint4 (t0 pair, t1 pair) ----
    // n = lane>>2, k0 = lane&3; t0: j=2k0, t1: j=16+2k0
    // .x=pack(w[j],w[j+1]) .y=pack(w[j+8],w[j+9]) .z/.w same for t1 (tap 31 padded)
    uint4* wf = (uint4*)(smem + OFF_W);
    for (int idx = tid; idx < 31 * 32; idx += NT) {
        const int i  = idx >> 5;
        const int ln = idx & 31;
        const int n  = ln >> 2;
        const int k0 = ln & 3;
        const float* wp = wgt + ((size_t)(n * CIN + ci) * KK + i) * KK;
        const int j0 = 2 * k0;
        const int j1 = 16 + 2 * k0;
        uint4 v;
        v.x = packh(wp[j0],     wp[j0 + 1]);
        v.y = packh(wp[j0 + 8], wp[j0 + 9]);
        v.z = packh(wp[j1],     wp[j1 + 1]);
        v.w = packh(wp[j1 + 8], (j1 + 9 < KK) ? wp[j1 + 9] : 0.0f);
        wf[idx] = v;
    }
    __syncthreads();

    // ---- compute ----
    const int m0  = lane >> 5 ? 0 : (lane >> 2);   // lane>>2
    const int k0l = lane & 3;
    const int par = (m0 + 1) & 1;

    float acc[2][RY][4];
#pragma unroll
    for (int s = 0; s < 2; ++s)
#pragma unroll
        for (int y = 0; y < RY; ++y)
#pragma unroll
            for (int q = 0; q < 4; ++q)
                acc[s][y][q] = 0.0f;

    // A diagonal words: a[j] at +16B*j from base; mma(s,t) uses a[u..u+2], u=2(s+t)
    const int lq0 = wid * 32 + 1 + m0 + 2 * k0l;
    const uint32_t aoff0 = (uint32_t)(par * (WPC * 4) + (((lq0 - par) >> 1) << 2));
    const uint32_t sa_base = sb + OFF_SA;
    const uint32_t b_base4 = sb + OFF_W + (uint32_t)lane * 16u;

    const int rlo = (Y0 - 15 > 0) ? Y0 - 15 : 0;
    const int rhi = (Y0 + RY + 14 < HH - 1) ? Y0 + RY + 14 : HH - 1;
    // interior: id0 = r - Y0 + 15 in [7, 30] -> all 8 y8 valid
    const int ilo = (rlo > Y0 - 8)  ? rlo : Y0 - 8;
    const int ihi = (rhi < Y0 + 15) ? rhi : Y0 + 15;

    // ---- leading edge rows (guarded) ----
#pragma unroll 1
    for (int r = rlo; r < ilo; ++r) {
        const int rr  = r - (Y0 - 15);
        const int id0 = r - Y0 + 15;
        const uint32_t arow = sa_base + (uint32_t)rr * ROWB + aoff0;
        uint32_t a[7];
#pragma unroll
        for (int j = 0; j < 7; ++j) a[j] = lds32(arow + 16u * j);
#pragma unroll
        for (int y8 = 0; y8 < RY; ++y8) {
            const int i = id0 - y8;
            if ((unsigned)i <= 30u) {
                const uint2 b0 = lds64(b_base4 + (uint32_t)(i * 512));
                const uint2 b1 = lds64(b_base4 + (uint32_t)(i * 512) + 8u);
                mma16(acc[0][y8], a[0], a[1], a[1], a[2], b0.x, b0.y);
                mma16(acc[1][y8], a[2], a[3], a[3], a[4], b0.x, b0.y);
                mma16(acc[0][y8], a[2], a[3], a[3], a[4], b1.x, b1.y);
                mma16(acc[1][y8], a[4], a[5], a[5], a[6], b1.x, b1.y);
            }
        }
    }

    // ---- interior rows: B register ring, 1 LDS.128 per row ----
    if (ilo <= ihi) {
        uint4 b[RY];
        {
            const int id0f = ilo - Y0 + 15;
#pragma unroll
            for (int y8 = 0; y8 < RY; ++y8)
                b[y8] = lds128(b_base4 + (uint32_t)((id0f - y8) * 512));
        }
#pragma unroll 1
        for (int r = ilo; r <= ihi; ++r) {
            const int rr = r - (Y0 - 15);
            const uint32_t arow = sa_base + (uint32_t)rr * ROWB + aoff0;
            uint32_t a[7];
#pragma unroll
            for (int j = 0; j < 7; ++j) a[j] = lds32(arow + 16u * j);

#pragma unroll
            for (int y8 = 0; y8 < RY; ++y8) {
                mma16(acc[0][y8], a[0], a[1], a[1], a[2], b[y8].x, b[y8].y);
                mma16(acc[1][y8], a[2], a[3], a[3], a[4], b[y8].x, b[y8].y);
                mma16(acc[0][y8], a[2], a[3], a[3], a[4], b[y8].z, b[y8].w);
                mma16(acc[1][y8], a[4], a[5], a[5], a[6], b[y8].z, b[y8].w);
            }
            // rotate ring, pull in fragment for next row (i = id0+1 <= 30 guaranteed by r < ihi <= Y0+15)
            if (r < ihi) {
#pragma unroll
                for (int y8 = RY - 1; y8 >= 1; --y8) b[y8] = b[y8 - 1];
                b[0] = lds128(b_base4 + (uint32_t)((r + 1 - Y0 + 15) * 512));
            }
        }
    }

    // ---- trailing edge rows (guarded) ----
#pragma unroll 1
    for (int r = ihi + 1; r <= rhi; ++r) {
        const int rr  = r - (Y0 - 15);
        const int id0 = r - Y0 + 15;
        const uint32_t arow = sa_base + (uint32_t)rr * ROWB + aoff0;
        uint32_t a[7];
#pragma unroll
        for (int j = 0; j < 7; ++j) a[j] = lds32(arow + 16u * j);
#pragma unroll
        for (int y8 = 0; y8 < RY; ++y8) {
            const int i = id0 - y8;
            if ((unsigned)i <= 30u) {
                const uint2 b0 = lds64(b_base4 + (uint32_t)(i * 512));
                const uint2 b1 = lds64(b_base4 + (uint32_t)(i * 512) + 8u);
                mma16(acc[0][y8], a[0], a[1], a[1], a[2], b0.x, b0.y);
                mma16(acc[1][y8], a[2], a[3], a[3], a[4], b0.x, b0.y);
                mma16(acc[0][y8], a[2], a[3], a[3], a[4], b1.x, b1.y);
                mma16(acc[1][y8], a[4], a[5], a[5], a[6], b1.x, b1.y);
            }
        }
    }

    // ---- epilogue: D c0:(m0,2k0) c1:(m0,2k0+1) c2:(m0+8,2k0) c3:(m0+8,2k0+1) ----
    const float bv  = bias[ci];
    const int co0   = 2 * k0l;
    const size_t plane = (size_t)CIN * HH * WW;

#pragma unroll
    for (int s = 0; s < 2; ++s) {
        const int px = X0 + wid * 32 + s * 16 + m0;
#pragma unroll
        for (int y8 = 0; y8 < RY; ++y8) {
            const int y = Y0 + y8;
            float* b0p = out + (((size_t)co0 * CIN + ci) * HH + y) * WW + px;
            float* b1p = b0p + plane;
            b0p[0] = acc[s][y8][0] + bv;
            b1p[0] = acc[s][y8][1] + bv;
            b0p[8] = acc[s][y8][2] + bv;
            b1p[8] = acc[s][y8][3] + bv;
        }
    }
}

extern "C" void kernel_launch(void* const* d_in, const int* in_sizes, int n_in,
                              void* d_out, int out_size)
{
    const float* sig  = (const float*)d_in[0];   // [1, 8, 1024, 1024]
    const float* wgt  = (const float*)d_in[1];   // [8, 8, 31, 31]
    const float* bias = (const float*)d_in[2];   // [8]
    float* out = (float*)d_out;                  // [8, 8, 1024, 1024]

    cudaFuncSetAttribute(conv_mma_kernel,
                         cudaFuncAttributeMaxDynamicSharedMemorySize, SMEM_TOTAL);
    dim3 grid(WW / TXC, HH / RY, CIN);           // (4, 128, 8) = 4096 blocks
    conv_mma_kernel<<<grid, NT, SMEM_TOTAL>>>(sig, wgt, bias, out);
}